// round 16
// baseline (speedup 1.0000x reference)
#include <cuda_runtime.h>
#include <cuda_fp16.h>
#include <cstdint>

// TpsGridGen: theta (64,50) -> grid (64,256,192,2) fp32
// R16: m16n8k16 HMMA, batch-split for occupancy.
//   Block = 128 px x 32 batches (64 n-rows). Grid (384, 2) = 768 blocks
//   -> 20.8 warps/SM (2x R15) with UNCHANGED total B-fragment LDS.
//   Warp = 32 px (2 m-tiles) x 64 n (8 n-tiles). Padded 17-word fragment
//   rows (conflict-free). fp16 hi/lo 3-pass, serial f32 accum.

#define OUT_H 256
#define OUT_W 192
#define NPX   (OUT_H * OUT_W)
#define NCP   25
#define NK    28
#define PXB   128
#define NTHR  128
#define NROW  64      // n-rows per block (= 32 batches)

__host__ __device__ constexpr float cpx(int n) { return 0.5f * (float)(n / 5) - 1.0f; }
__host__ __device__ constexpr float cpy(int n) { return 0.5f * (float)(n % 5) - 1.0f; }

// ---------------------------------------------------------------------------
// Compile-time inv(L), transposed to [m][k], RBF rows (k<25) pre-scaled by ln2
// ---------------------------------------------------------------------------
constexpr double cfabs(double x) { return x < 0.0 ? -x : x; }

constexpr double clog(double x) {
    int e = 0;
    while (x >= 1.4142135623730951) { x *= 0.5; e++; }
    while (x <  0.7071067811865476) { x *= 2.0; e--; }
    double t = (x - 1.0) / (x + 1.0), t2 = t * t, p = t, s = 0.0;
    for (int k = 0; k < 27; k++) { s += p / (double)(2 * k + 1); p *= t2; }
    return 2.0 * s + (double)e * 0.6931471805599453094172321214581766;
}

struct alignas(16) TPSLiS { float v[NCP][NK]; };   // [m][k]

constexpr TPSLiS make_lis() {
    const double ax[5] = {-1.0, -0.5, 0.0, 0.5, 1.0};
    double PX[NCP] = {}, PY[NCP] = {};
    for (int i = 0; i < 5; i++)
        for (int j = 0; j < 5; j++) { PX[i*5+j] = ax[i]; PY[i*5+j] = ax[j]; }

    double a[28][56] = {};
    for (int i = 0; i < 25; i++)
        for (int j = 0; j < 25; j++)
            if (i != j) {
                double dx = PX[i]-PX[j], dy = PY[i]-PY[j];
                double d2 = dx*dx + dy*dy;
                a[i][j] = d2 * clog(d2);
            }
    for (int i = 0; i < 25; i++) {
        a[i][25] = 1.0; a[i][26] = PX[i]; a[i][27] = PY[i];
        a[25][i] = 1.0; a[26][i] = PX[i]; a[27][i] = PY[i];
    }
    for (int i = 0; i < 28; i++) a[i][28+i] = 1.0;

    for (int k = 0; k < 28; k++) {
        int piv = k; double best = cfabs(a[k][k]);
        for (int i = k+1; i < 28; i++) {
            double v = cfabs(a[i][k]);
            if (v > best) { best = v; piv = i; }
        }
        if (piv != k)
            for (int j = 0; j < 56; j++) {
                double t = a[k][j]; a[k][j] = a[piv][j]; a[piv][j] = t;
            }
        double inv = 1.0 / a[k][k];
        for (int j = 0; j < 56; j++) a[k][j] *= inv;
        for (int i = 0; i < 28; i++) {
            if (i == k) continue;
            double f = a[i][k];
            if (f != 0.0)
                for (int j = 0; j < 56; j++) a[i][j] -= f * a[k][j];
        }
    }
    const double LN2 = 0.6931471805599453094172321214581766;
    TPSLiS r{};
    for (int m = 0; m < NCP; m++)
        for (int k = 0; k < NK; k++)
            r.v[m][k] = (float)(((k < 25) ? LN2 : 1.0) * a[k][28 + m]);
    return r;
}

__device__ const TPSLiS g_lis = make_lis();

// Compile-time linspace tables (numpy fp64 semantics, endpoint exact).
struct alignas(16) GridTab { float g[448]; };   // [0..191]=gx, [192..447]=gy

constexpr GridTab make_grid() {
    GridTab r{};
    for (int w = 0; w < OUT_W; w++)
        r.g[w] = (float)(-1.0 + (double)w * (2.0 / (double)(OUT_W - 1)));
    r.g[OUT_W - 1] = 1.0f;
    for (int h = 0; h < OUT_H; h++)
        r.g[192 + h] = (float)(-1.0 + (double)h * (2.0 / (double)(OUT_H - 1)));
    r.g[192 + OUT_H - 1] = 1.0f;
    return r;
}

__device__ const GridTab g_grid = make_grid();

// ---------------------------------------------------------------------------
__device__ __forceinline__ uint32_t h2bits(__half2 h) {
    return *reinterpret_cast<uint32_t*>(&h);
}

__device__ __forceinline__ void hilo(float v0, float v1, uint32_t& hi, uint32_t& lo) {
    __half2 h = __floats2half2_rn(v0, v1);
    float r0 = v0 - __low2float(h);
    float r1 = v1 - __high2float(h);
    hi = h2bits(h);
    lo = h2bits(__floats2half2_rn(r0, r1));
}

__device__ __forceinline__ void mma16n8k16(float& d0, float& d1, float& d2, float& d3,
                                           uint32_t a0, uint32_t a1, uint32_t a2,
                                           uint32_t a3, uint32_t b0, uint32_t b1) {
    asm("mma.sync.aligned.m16n8k16.row.col.f32.f16.f16.f32 "
        "{%0,%1,%2,%3},{%4,%5,%6,%7},{%8,%9},{%0,%1,%2,%3};"
        : "+f"(d0), "+f"(d1), "+f"(d2), "+f"(d3)
        : "r"(a0), "r"(a1), "r"(a2), "r"(a3), "r"(b0), "r"(b1));
}

// ---------------------------------------------------------------------------
// Kernel. grid (384, 2), block 128. Block = 128 px x 32 batches (64 n-rows).
// Warp = 32 px (2 m-tiles) x 64 n (8 n-tiles).
// ---------------------------------------------------------------------------
__global__ __launch_bounds__(NTHR) void tps_mma_kernel(
    const float* __restrict__ theta, float2* __restrict__ out) {

    __shared__ __align__(16) float s_li[NCP * NK];            // 2.8 KB
    __shared__ uint32_t s_uh[PXB][17], s_ul[PXB][17];         // 17.4 KB
    __shared__ uint32_t s_ch[NROW][17], s_cl[NROW][17];       // 8.7 KB

    const int tid = threadIdx.x;
    const int wid = tid >> 5;
    const int lid = tid & 31;
    const int gy  = blockIdx.y;          // batch-half (32 batches)

    // ---- Stage Li ----
    {
        const float4* ls = (const float4*)&g_lis;
        for (int i = tid; i < 175; i += NTHR) ((float4*)s_li)[i] = ls[i];
    }
    __syncthreads();

    // ---- Phase A: thread = (n-row 0..63, k-half). theta from L2 ----
    {
        const int nrow  = tid & 63;                 // local n-row
        const int khalf = tid >> 6;                 // 0: k0..15, 1: k16..27
        const int ng    = gy * NROW + nrow;         // global n-row
        const int b     = ng >> 1;
        const int axis  = ng & 1;
        const float* trow = theta + b * 50 + axis * NCP;

        const int klo = khalf * 16;
        const int nk  = khalf ? 12 : 16;            // real k count in this half
        float acc[16];
#pragma unroll
        for (int k = 0; k < 16; k++) acc[k] = 0.f;
#pragma unroll
        for (int m = 0; m < NCP; m++) {
            const float q = trow[m] + (axis ? cpy(m) : cpx(m));
            const float* lr = s_li + m * NK + klo;
#pragma unroll
            for (int k = 0; k < 16; k++)
                if (k < nk) acc[k] = fmaf(lr[k], q, acc[k]);
        }
        const int kp0 = khalf * 8;
#pragma unroll
        for (int kp = 0; kp < 8; kp++) {
            if (khalf && kp >= 6) {                 // pads kp 14,15
                s_ch[nrow][kp0 + kp] = 0;
                s_cl[nrow][kp0 + kp] = 0;
            } else {
                hilo(acc[2*kp], acc[2*kp+1],
                     s_ch[nrow][kp0 + kp], s_cl[nrow][kp0 + kp]);
            }
        }
    }

    // ---- U build: thread = pixel ----
    {
        const int px  = tid;
        const int pid = blockIdx.x * PXB + px;
        const int h = pid / OUT_W;
        const int w = pid - h * OUT_W;
        const float gx = g_grid.g[w];
        const float gyv = g_grid.g[192 + h];
        float u[NK];
#pragma unroll
        for (int n = 0; n < NCP; n++) {
            const float dx = gx - cpx(n);
            const float dy = gyv - cpy(n);
            const float d2 = dx * dx + dy * dy;
            u[n] = (d2 == 0.0f) ? 0.0f : d2 * __log2f(d2);
        }
        u[25] = 1.0f; u[26] = gx; u[27] = gyv;
#pragma unroll
        for (int kp = 0; kp < 14; kp++)
            hilo(u[2*kp], u[2*kp+1], s_uh[px][kp], s_ul[px][kp]);
        s_uh[px][14] = 0; s_uh[px][15] = 0;
        s_ul[px][14] = 0; s_ul[px][15] = 0;
    }
    __syncthreads();

    // ---- MMA: warp = 32 px (2 mt) x 64 n (8 nt), 2 k16-chunks, 3 passes ----
    const int g4  = lid >> 2;     // 0..7
    const int tig = lid & 3;      // 0..3

    uint32_t ah[2][8], al[2][8];
#pragma unroll
    for (int mt = 0; mt < 2; mt++) {
        const int r0 = wid * 32 + mt * 16 + g4;
        const int r1 = r0 + 8;
#pragma unroll
        for (int c16 = 0; c16 < 2; c16++) {
            const int kpA = 8 * c16 + tig;
            const int kpB = 8 * c16 + 4 + tig;
            ah[mt][4*c16+0] = s_uh[r0][kpA];
            ah[mt][4*c16+1] = s_uh[r1][kpA];
            ah[mt][4*c16+2] = s_uh[r0][kpB];
            ah[mt][4*c16+3] = s_uh[r1][kpB];
            al[mt][4*c16+0] = s_ul[r0][kpA];
            al[mt][4*c16+1] = s_ul[r1][kpA];
            al[mt][4*c16+2] = s_ul[r0][kpB];
            al[mt][4*c16+3] = s_ul[r1][kpB];
        }
    }

    const int pxw = blockIdx.x * PXB + wid * 32;
#pragma unroll
    for (int nt = 0; nt < 8; nt++) {
        const int n = nt * 8 + g4;                // local n-row for B frag
        uint32_t bh[4], bl[4];
        bh[0] = s_ch[n][tig];      bh[1] = s_ch[n][4 + tig];
        bh[2] = s_ch[n][8 + tig];  bh[3] = s_ch[n][12 + tig];
        bl[0] = s_cl[n][tig];      bl[1] = s_cl[n][4 + tig];
        bl[2] = s_cl[n][8 + tig];  bl[3] = s_cl[n][12 + tig];

        const int bg = gy * 32 + nt * 4 + tig;    // global batch
        float2* o = out + (size_t)bg * NPX + pxw;
#pragma unroll
        for (int mt = 0; mt < 2; mt++) {
            float d0 = 0.f, d1 = 0.f, d2 = 0.f, d3 = 0.f;
            mma16n8k16(d0,d1,d2,d3, ah[mt][0],ah[mt][1],ah[mt][2],ah[mt][3], bh[0],bh[1]);
            mma16n8k16(d0,d1,d2,d3, ah[mt][0],ah[mt][1],ah[mt][2],ah[mt][3], bl[0],bl[1]);
            mma16n8k16(d0,d1,d2,d3, al[mt][0],al[mt][1],al[mt][2],al[mt][3], bh[0],bh[1]);
            mma16n8k16(d0,d1,d2,d3, ah[mt][4],ah[mt][5],ah[mt][6],ah[mt][7], bh[2],bh[3]);
            mma16n8k16(d0,d1,d2,d3, ah[mt][4],ah[mt][5],ah[mt][6],ah[mt][7], bl[2],bl[3]);
            mma16n8k16(d0,d1,d2,d3, al[mt][4],al[mt][5],al[mt][6],al[mt][7], bh[2],bh[3]);

            o[mt * 16 + g4]     = make_float2(d0, d1);
            o[mt * 16 + g4 + 8] = make_float2(d2, d3);
        }
    }
}

// ---------------------------------------------------------------------------
extern "C" void kernel_launch(void* const* d_in, const int* in_sizes, int n_in,
                              void* d_out, int out_size) {
    const float* theta = (const float*)d_in[0];
    (void)in_sizes; (void)n_in; (void)out_size;

    dim3 grid(NPX / PXB, 2);    // (384, 2)
    tps_mma_kernel<<<grid, NTHR>>>(theta, (float2*)d_out);
}